// round 3
// baseline (speedup 1.0000x reference)
#include <cuda_runtime.h>

#define D_MODEL 1024
#define SEQLEN  2048
#define BATCH   4
#define NHEADS  16
#define HDIM    64
#define MROWS   (BATCH * SEQLEN)   /* 8192 */
#define INV_TAU (1.0f / 0.07f)

typedef unsigned long long ull;

// Scratch (allocation-free rule: __device__ globals)
__device__ float g_Qp[MROWS * D_MODEL];
__device__ float g_Kp[MROWS * D_MODEL];
__device__ float g_Vp[MROWS * D_MODEL];
__device__ float g_Ao[MROWS * D_MODEL];

// ---- packed f32x2 helpers (ptxas never emits FFMA2 from C++) ----
__device__ __forceinline__ void ffma2(ull& d, ull a, ull b) {
    asm("fma.rn.f32x2 %0, %1, %2, %0;" : "+l"(d) : "l"(a), "l"(b));
}
__device__ __forceinline__ ull fmul2(ull a, ull b) {
    ull r; asm("mul.rn.f32x2 %0, %1, %2;" : "=l"(r) : "l"(a), "l"(b)); return r;
}
__device__ __forceinline__ ull pack2(float x, float y) {
    ull r; asm("mov.b64 %0, {%1, %2};" : "=l"(r) : "f"(x), "f"(y)); return r;
}
__device__ __forceinline__ float2 upk2(ull v) {
    float2 f; asm("mov.b64 {%0, %1}, %2;" : "=f"(f.x), "=f"(f.y) : "l"(v)); return f;
}
__device__ __forceinline__ float hadd2(ull v) {
    float2 f = upk2(v); return f.x + f.y;
}

// ---------------------------------------------------------------------------
// GEMM: C[M,N] = A[M,K] @ W[N,K]^T + bias[N]
// 128x128 tile, BK=16, 256 threads, 8x8 per thread, k-paired FFMA2.
// Lanes of each 64-bit accumulator hold even/odd-k partial sums.
// ---------------------------------------------------------------------------
__global__ __launch_bounds__(256, 1) void gemm_bias_kernel(
    const float* __restrict__ A, const float* __restrict__ W,
    const float* __restrict__ bias, float* __restrict__ C,
    int M, int N, int K)
{
    __shared__ ull As2[128 * 9];   // [m][k-pair], stride 9 (pad)
    __shared__ ull Bs2[128 * 8];   // [n][k-pair], XOR-swizzled by (n>>3)&7

    const int tid  = threadIdx.x;
    const int brow = blockIdx.y * 128;
    const int bcol = blockIdx.x * 128;
    const int ty   = tid >> 4;          // 0..15 -> rows ty*8..+7
    const int tx   = tid & 15;          // 0..15 -> cols tx*8..+7

    // A loader: row = tid>>1, k-half = tid&1 (8 floats each)
    const int alr = tid >> 1;
    const int alh = tid & 1;
    // W loader: scattered rows so smem writes are conflict-light
    const int wlr = ((tid & 15) << 3) | ((tid >> 4) & 7);
    const int wlh = tid >> 7;

    const float* Ap = A + (size_t)(brow + alr) * K + alh * 8;
    const float* Wp = W + (size_t)(bcol + wlr) * K + wlh * 8;

    ull acc[8][8];
#pragma unroll
    for (int i = 0; i < 8; i++)
#pragma unroll
        for (int j = 0; j < 8; j++) acc[i][j] = 0ull;

    const int bswz = (wlr >> 3) & 7;

    for (int k0 = 0; k0 < K; k0 += 16) {
        float4 a0 = *(const float4*)(Ap + k0);
        float4 a1 = *(const float4*)(Ap + k0 + 4);
        float4 w0 = *(const float4*)(Wp + k0);
        float4 w1 = *(const float4*)(Wp + k0 + 4);
        __syncthreads();
        {
            ull* ap = &As2[alr * 9 + alh * 4];
            ap[0] = pack2(a0.x, a0.y); ap[1] = pack2(a0.z, a0.w);
            ap[2] = pack2(a1.x, a1.y); ap[3] = pack2(a1.z, a1.w);
            ull* bp = &Bs2[wlr * 8];
            int p0 = wlh * 4;
            bp[(p0 + 0) ^ bswz] = pack2(w0.x, w0.y);
            bp[(p0 + 1) ^ bswz] = pack2(w0.z, w0.w);
            bp[(p0 + 2) ^ bswz] = pack2(w1.x, w1.y);
            bp[(p0 + 3) ^ bswz] = pack2(w1.z, w1.w);
        }
        __syncthreads();
#pragma unroll
        for (int pk = 0; pk < 8; pk++) {
            ull a2[8], b2[8];
#pragma unroll
            for (int i = 0; i < 8; i++)
                a2[i] = As2[(ty * 8 + i) * 9 + pk];
#pragma unroll
            for (int j = 0; j < 8; j++)
                b2[j] = Bs2[(tx * 8 + j) * 8 + (pk ^ (tx & 7))];
#pragma unroll
            for (int i = 0; i < 8; i++)
#pragma unroll
                for (int j = 0; j < 8; j++)
                    ffma2(acc[i][j], a2[i], b2[j]);
        }
    }

    float bv[8];
    *(float4*)&bv[0] = *(const float4*)(bias + bcol + tx * 8);
    *(float4*)&bv[4] = *(const float4*)(bias + bcol + tx * 8 + 4);
#pragma unroll
    for (int i = 0; i < 8; i++) {
        float* Cp = C + (size_t)(brow + ty * 8 + i) * N + bcol + tx * 8;
        float4 o0, o1;
        o0.x = hadd2(acc[i][0]) + bv[0]; o0.y = hadd2(acc[i][1]) + bv[1];
        o0.z = hadd2(acc[i][2]) + bv[2]; o0.w = hadd2(acc[i][3]) + bv[3];
        o1.x = hadd2(acc[i][4]) + bv[4]; o1.y = hadd2(acc[i][5]) + bv[5];
        o1.z = hadd2(acc[i][6]) + bv[6]; o1.w = hadd2(acc[i][7]) + bv[7];
        *(float4*)Cp       = o0;
        *(float4*)(Cp + 4) = o1;
    }
}

// ---------------------------------------------------------------------------
// Per-head L2 normalize
// ---------------------------------------------------------------------------
__global__ __launch_bounds__(256) void l2norm_kernel(float* __restrict__ X, int nchunks)
{
    int gid  = blockIdx.x * blockDim.x + threadIdx.x;
    int warp = gid >> 5;
    int lane = gid & 31;
    if (warp >= nchunks) return;
    float* p = X + (size_t)warp * 64 + lane * 2;
    float2 v = *(float2*)p;
    float ss = v.x * v.x + v.y * v.y;
#pragma unroll
    for (int m = 16; m > 0; m >>= 1)
        ss += __shfl_xor_sync(0xffffffffu, ss, m);
    float inv = 1.0f / fmaxf(sqrtf(ss), 1e-12f);
    v.x *= inv; v.y *= inv;
    *(float2*)p = v;
}

// ---------------------------------------------------------------------------
// Flash attention, FFMA2 (k-paired) version.
// Smem tiles stored as 64-bit pairs with XOR swizzle (p ^ (row>>2 & 15)).
// Q: [m][d-pair], K: [n][d-pair] (reused for P: [m][k-pair]),
// V: TRANSPOSED [c][k-pair] so the PV loop is also k-paired.
// ---------------------------------------------------------------------------
__global__ __launch_bounds__(256) void attn_kernel(
    const float* __restrict__ Q, const float* __restrict__ K,
    const float* __restrict__ V, float* __restrict__ O)
{
    __shared__ ull Qs2[64 * 32];
    __shared__ ull KPs2[64 * 32];   // K tile, then reused as P
    __shared__ ull Vt2[64 * 32];    // transposed V: row=c, col=k-pair

    const int tid = threadIdx.x;
    const int qt  = blockIdx.x;
    const int bh  = blockIdx.y;
    const int b   = bh >> 4, h = bh & 15;
    const int base = (b * SEQLEN) * D_MODEL + h * HDIM;
    const int ty = tid >> 4, tx = tid & 15;
    const int r0 = ty * 4;
    const int n0 = tx * 4;

    // Load Q tile (scaled by 1/tau), swizzled pairs
#pragma unroll
    for (int i = 0; i < 4; i++) {
        int idx = tid + i * 256;
        int r = idx >> 4, c4 = idx & 15;
        float4 v = *(const float4*)(Q + base + (qt * 64 + r) * D_MODEL + c4 * 4);
        int swz = (r >> 2) & 15;
        ull* qp = &Qs2[r * 32];
        qp[(c4 * 2)     ^ swz] = pack2(v.x * INV_TAU, v.y * INV_TAU);
        qp[(c4 * 2 + 1) ^ swz] = pack2(v.z * INV_TAU, v.w * INV_TAU);
    }

    float m_i[4], l_i[4];
    ull o2[4][4];
#pragma unroll
    for (int i = 0; i < 4; i++) {
        m_i[i] = -1e30f;
        l_i[i] = 0.f;
#pragma unroll
        for (int c = 0; c < 4; c++) o2[i][c] = 0ull;
    }

    float* Vsf = (float*)Vt2;

    for (int kt = 0; kt < SEQLEN / 64; kt++) {
        __syncthreads();   // previous PV readers done before overwriting K/V
#pragma unroll
        for (int i = 0; i < 4; i++) {
            int idx = tid + i * 256;
            int r = idx >> 4, c4 = idx & 15;
            float4 kv = *(const float4*)(K + base + (kt * 64 + r) * D_MODEL + c4 * 4);
            int swz = (r >> 2) & 15;
            ull* kp = &KPs2[r * 32];
            kp[(c4 * 2)     ^ swz] = pack2(kv.x, kv.y);
            kp[(c4 * 2 + 1) ^ swz] = pack2(kv.z, kv.w);
            float4 vv = *(const float4*)(V + base + (kt * 64 + r) * D_MODEL + c4 * 4);
            // transpose into Vt2: element (k=r, c=4*c4+cc)
            int ph = r >> 1, hf = r & 1;
#pragma unroll
            for (int cc = 0; cc < 4; cc++) {
                int c = c4 * 4 + cc;
                float val = (cc == 0) ? vv.x : (cc == 1) ? vv.y : (cc == 2) ? vv.z : vv.w;
                Vsf[(c * 32 + (ph ^ ((c >> 2) & 15))) * 2 + hf] = val;
            }
        }
        __syncthreads();

        // S = (Q/tau) @ K^T, k-paired
        ull s2[4][4];
#pragma unroll
        for (int i = 0; i < 4; i++)
#pragma unroll
            for (int j = 0; j < 4; j++) s2[i][j] = 0ull;

#pragma unroll 8
        for (int p = 0; p < 32; p++) {
            ull q2[4], k2[4];
#pragma unroll
            for (int i = 0; i < 4; i++) q2[i] = Qs2[(r0 + i) * 32 + (p ^ ty)];
#pragma unroll
            for (int j = 0; j < 4; j++) k2[j] = KPs2[(n0 + j) * 32 + (p ^ tx)];
#pragma unroll
            for (int i = 0; i < 4; i++)
#pragma unroll
                for (int j = 0; j < 4; j++)
                    ffma2(s2[i][j], q2[i], k2[j]);
        }
        __syncthreads();   // K reads done before P overwrites buffer

        // Online softmax; write P (paired) into KPs2
#pragma unroll
        for (int i = 0; i < 4; i++) {
            float s0 = hadd2(s2[i][0]), s1 = hadd2(s2[i][1]);
            float s0b = hadd2(s2[i][2]), s1b = hadd2(s2[i][3]);
            float rmax = fmaxf(fmaxf(s0, s1), fmaxf(s0b, s1b));
            rmax = fmaxf(rmax, __shfl_xor_sync(0xffffffffu, rmax, 1));
            rmax = fmaxf(rmax, __shfl_xor_sync(0xffffffffu, rmax, 2));
            rmax = fmaxf(rmax, __shfl_xor_sync(0xffffffffu, rmax, 4));
            rmax = fmaxf(rmax, __shfl_xor_sync(0xffffffffu, rmax, 8));
            float mn = fmaxf(m_i[i], rmax);
            float p0 = __expf(s0 - mn);
            float p1 = __expf(s1 - mn);
            float p2 = __expf(s0b - mn);
            float p3 = __expf(s1b - mn);
            float rs = p0 + p1 + p2 + p3;
            rs += __shfl_xor_sync(0xffffffffu, rs, 1);
            rs += __shfl_xor_sync(0xffffffffu, rs, 2);
            rs += __shfl_xor_sync(0xffffffffu, rs, 4);
            rs += __shfl_xor_sync(0xffffffffu, rs, 8);
            float sc = __expf(m_i[i] - mn);
            l_i[i] = l_i[i] * sc + rs;
            m_i[i] = mn;
            ull sc2 = pack2(sc, sc);
#pragma unroll
            for (int c = 0; c < 4; c++) o2[i][c] = fmul2(o2[i][c], sc2);
            ull* pp = &KPs2[(r0 + i) * 32];
            pp[(tx * 2)     ^ ty] = pack2(p0, p1);
            pp[(tx * 2 + 1) ^ ty] = pack2(p2, p3);
        }
        __syncthreads();

        // O += P @ V, k-paired (V transposed in smem)
#pragma unroll 8
        for (int p = 0; p < 32; p++) {
            ull p2r[4], v2[4];
#pragma unroll
            for (int i = 0; i < 4; i++) p2r[i] = KPs2[(r0 + i) * 32 + (p ^ ty)];
#pragma unroll
            for (int cc = 0; cc < 4; cc++) v2[cc] = Vt2[(n0 + cc) * 32 + (p ^ tx)];
#pragma unroll
            for (int i = 0; i < 4; i++)
#pragma unroll
                for (int cc = 0; cc < 4; cc++)
                    ffma2(o2[i][cc], p2r[i], v2[cc]);
        }
    }

#pragma unroll
    for (int i = 0; i < 4; i++) {
        float inv = 1.0f / l_i[i];
        float4 r;
        r.x = hadd2(o2[i][0]) * inv;
        r.y = hadd2(o2[i][1]) * inv;
        r.z = hadd2(o2[i][2]) * inv;
        r.w = hadd2(o2[i][3]) * inv;
        *(float4*)(O + base + (qt * 64 + r0 + i) * D_MODEL + tx * 4) = r;
    }
}

// ---------------------------------------------------------------------------
extern "C" void kernel_launch(void* const* d_in, const int* in_sizes, int n_in,
                              void* d_out, int out_size)
{
    const float* q  = (const float*)d_in[0];
    const float* k  = (const float*)d_in[1];
    const float* v  = (const float*)d_in[2];
    const float* Wq = (const float*)d_in[3];
    const float* bq = (const float*)d_in[4];
    const float* Wk = (const float*)d_in[5];
    const float* bk = (const float*)d_in[6];
    const float* Wv = (const float*)d_in[7];
    const float* bv = (const float*)d_in[8];
    const float* Wo = (const float*)d_in[9];
    const float* bo = (const float*)d_in[10];
    float* out = (float*)d_out;

    float *Qp, *Kp, *Vp, *Ao;
    cudaGetSymbolAddress((void**)&Qp, g_Qp);
    cudaGetSymbolAddress((void**)&Kp, g_Kp);
    cudaGetSymbolAddress((void**)&Vp, g_Vp);
    cudaGetSymbolAddress((void**)&Ao, g_Ao);

    dim3 ggrid(D_MODEL / 128, MROWS / 128);   // (8, 64)

    gemm_bias_kernel<<<ggrid, 256>>>(q, Wq, bq, Qp, MROWS, D_MODEL, D_MODEL);
    gemm_bias_kernel<<<ggrid, 256>>>(k, Wk, bk, Kp, MROWS, D_MODEL, D_MODEL);
    gemm_bias_kernel<<<ggrid, 256>>>(v, Wv, bv, Vp, MROWS, D_MODEL, D_MODEL);

    const int nchunks = MROWS * NHEADS;       // 131072
    l2norm_kernel<<<nchunks / 8, 256>>>(Qp, nchunks);
    l2norm_kernel<<<nchunks / 8, 256>>>(Kp, nchunks);

    attn_kernel<<<dim3(SEQLEN / 64, BATCH * NHEADS), 256>>>(Qp, Kp, Vp, Ao);

    gemm_bias_kernel<<<ggrid, 256>>>(Ao, Wo, bo, out, MROWS, D_MODEL, D_MODEL);
}

// round 4
// speedup vs baseline: 1.4978x; 1.4978x over previous
#include <cuda_runtime.h>
#include <cstdint>

#define D_MODEL 1024
#define SEQLEN  2048
#define BATCH   4
#define NHEADS  16
#define HDIM    64
#define MROWS   (BATCH * SEQLEN)   /* 8192 */
#define INV_TAU (1.0f / 0.07f)

// Scratch (allocation-free rule: __device__ globals)
__device__ float g_Qp[MROWS * D_MODEL];
__device__ float g_Kp[MROWS * D_MODEL];
__device__ float g_Vp[MROWS * D_MODEL];
__device__ float g_Ao[MROWS * D_MODEL];

// ---- tf32 helpers ----
__device__ __forceinline__ uint32_t f2tf32(float f) {
    uint32_t r; asm("cvt.rna.tf32.f32 %0, %1;" : "=r"(r) : "f"(f)); return r;
}
__device__ __forceinline__ void mma8(float* c, const uint32_t* a, const uint32_t* b) {
    asm volatile("mma.sync.aligned.m16n8k8.row.col.f32.tf32.tf32.f32 "
        "{%0,%1,%2,%3},{%4,%5,%6,%7},{%8,%9},{%0,%1,%2,%3};"
        : "+f"(c[0]), "+f"(c[1]), "+f"(c[2]), "+f"(c[3])
        : "r"(a[0]), "r"(a[1]), "r"(a[2]), "r"(a[3]), "r"(b[0]), "r"(b[1]));
}

// ---------------------------------------------------------------------------
// Tensor-core GEMM: C[M,N] = A[M,K] @ W[N,K]^T + bias[N]
// Block 128x128, BK=16, 256 threads (8 warps as 2x4), warp tile 64x32.
// SPLIT: 3-pass split-tf32 (~fp32 quality).
// Smem stride 20 words: fragment reads are bank-conflict-free.
// ---------------------------------------------------------------------------
template<bool SPLIT>
__global__ __launch_bounds__(256) void gemm_tc(
    const float* __restrict__ A, const float* __restrict__ W,
    const float* __restrict__ bias, float* __restrict__ C)
{
    const int K = D_MODEL, N = D_MODEL;
    __shared__ uint32_t Ah[128 * 20];
    __shared__ uint32_t Bh[128 * 20];
    __shared__ uint32_t Al[SPLIT ? 128 * 20 : 1];
    __shared__ uint32_t Bl[SPLIT ? 128 * 20 : 1];

    const int t    = threadIdx.x;
    const int lane = t & 31, wid = t >> 5;
    const int wm   = wid >> 2, wn = wid & 3;         // 2 x 4 warp grid
    const int brow = blockIdx.y * 128, bcol = blockIdx.x * 128;
    const int lr   = t >> 1;                          // 0..127
    const int lh   = (t & 1) * 8;                     // k offset 0 or 8

    const float* Ap = A + (size_t)(brow + lr) * K + lh;
    const float* Wp = W + (size_t)(bcol + lr) * K + lh;

    float acc[4][4][4];
#pragma unroll
    for (int mt = 0; mt < 4; mt++)
#pragma unroll
        for (int nt = 0; nt < 4; nt++)
#pragma unroll
            for (int i = 0; i < 4; i++) acc[mt][nt][i] = 0.f;

    float4 pa0 = *(const float4*)Ap,       pa1 = *(const float4*)(Ap + 4);
    float4 pw0 = *(const float4*)Wp,       pw1 = *(const float4*)(Wp + 4);

    for (int k0 = 0; k0 < K; k0 += 16) {
        __syncthreads();
        {
            const int bi = lr * 20 + lh;
            const float* fa = &pa0.x;  // pa0,pa1 contiguous on stack
            const float* fw = &pw0.x;
#pragma unroll
            for (int j = 0; j < 4; j++) {
                uint32_t h;
                h = f2tf32(fa[j]);  Ah[bi + j] = h;
                if (SPLIT) Al[bi + j] = f2tf32(fa[j] - __uint_as_float(h));
                float fa1j = (&pa1.x)[j];
                h = f2tf32(fa1j);   Ah[bi + 4 + j] = h;
                if (SPLIT) Al[bi + 4 + j] = f2tf32(fa1j - __uint_as_float(h));
                h = f2tf32(fw[j]);  Bh[bi + j] = h;
                if (SPLIT) Bl[bi + j] = f2tf32(fw[j] - __uint_as_float(h));
                float fw1j = (&pw1.x)[j];
                h = f2tf32(fw1j);   Bh[bi + 4 + j] = h;
                if (SPLIT) Bl[bi + 4 + j] = f2tf32(fw1j - __uint_as_float(h));
            }
        }
        __syncthreads();
        if (k0 + 16 < K) {
            Ap += 16; Wp += 16;
            pa0 = *(const float4*)Ap; pa1 = *(const float4*)(Ap + 4);
            pw0 = *(const float4*)Wp; pw1 = *(const float4*)(Wp + 4);
        }
#pragma unroll
        for (int c = 0; c < 2; c++) {
            const int kk = (lane & 3) + c * 8;
            uint32_t ah[4][4], bh[4][2];
            uint32_t al[SPLIT ? 4 : 1][4], bl[SPLIT ? 4 : 1][2];
#pragma unroll
            for (int mt = 0; mt < 4; mt++) {
                int r = wm * 64 + mt * 16 + (lane >> 2);
                ah[mt][0] = Ah[r * 20 + kk];
                ah[mt][1] = Ah[(r + 8) * 20 + kk];
                ah[mt][2] = Ah[r * 20 + kk + 4];
                ah[mt][3] = Ah[(r + 8) * 20 + kk + 4];
                if (SPLIT) {
                    al[mt][0] = Al[r * 20 + kk];
                    al[mt][1] = Al[(r + 8) * 20 + kk];
                    al[mt][2] = Al[r * 20 + kk + 4];
                    al[mt][3] = Al[(r + 8) * 20 + kk + 4];
                }
            }
#pragma unroll
            for (int nt = 0; nt < 4; nt++) {
                int n = wn * 32 + nt * 8 + (lane >> 2);
                bh[nt][0] = Bh[n * 20 + kk];
                bh[nt][1] = Bh[n * 20 + kk + 4];
                if (SPLIT) {
                    bl[nt][0] = Bl[n * 20 + kk];
                    bl[nt][1] = Bl[n * 20 + kk + 4];
                }
            }
#pragma unroll
            for (int mt = 0; mt < 4; mt++)
#pragma unroll
                for (int nt = 0; nt < 4; nt++) {
                    mma8(acc[mt][nt], ah[mt], bh[nt]);
                    if (SPLIT) {
                        mma8(acc[mt][nt], ah[mt], bl[nt]);
                        mma8(acc[mt][nt], al[mt], bh[nt]);
                    }
                }
        }
    }

#pragma unroll
    for (int mt = 0; mt < 4; mt++)
#pragma unroll
        for (int nt = 0; nt < 4; nt++) {
            int gr = brow + wm * 64 + mt * 16 + (lane >> 2);
            int gc = bcol + wn * 32 + nt * 8 + (lane & 3) * 2;
            float2 bb = *(const float2*)(bias + gc);
            float2 o0 = make_float2(acc[mt][nt][0] + bb.x, acc[mt][nt][1] + bb.y);
            float2 o1 = make_float2(acc[mt][nt][2] + bb.x, acc[mt][nt][3] + bb.y);
            *(float2*)(C + (size_t)gr * N + gc)       = o0;
            *(float2*)(C + (size_t)(gr + 8) * N + gc) = o1;
        }
}

// ---------------------------------------------------------------------------
// Per-head L2 normalize
// ---------------------------------------------------------------------------
__global__ __launch_bounds__(256) void l2norm_kernel(float* __restrict__ X, int nchunks)
{
    int gid  = blockIdx.x * blockDim.x + threadIdx.x;
    int warp = gid >> 5;
    int lane = gid & 31;
    if (warp >= nchunks) return;
    float* p = X + (size_t)warp * 64 + lane * 2;
    float2 v = *(float2*)p;
    float ss = v.x * v.x + v.y * v.y;
#pragma unroll
    for (int m = 16; m > 0; m >>= 1)
        ss += __shfl_xor_sync(0xffffffffu, ss, m);
    float inv = 1.0f / fmaxf(sqrtf(ss), 1e-12f);
    v.x *= inv; v.y *= inv;
    *(float2*)p = v;
}

// ---------------------------------------------------------------------------
// Flash attention (tf32 mma). Grid (L/64, B*H), 128 threads (4 warps).
// Warp w owns q-rows [w*16, w*16+16). 32-key tiles.
// QK^T: 3-pass split-tf32 (tau-amplified). PV: single-pass tf32.
// Q hi/lo fragments kept in registers for the whole block.
// ---------------------------------------------------------------------------
__global__ __launch_bounds__(128) void attn_tc(
    const float* __restrict__ Q, const float* __restrict__ K,
    const float* __restrict__ V, float* __restrict__ O)
{
    __shared__ uint32_t KS[2 * 32 * 68];   // K hi | K lo (also Q staging at start)
    __shared__ uint32_t Vs[32 * 72];
    __shared__ float    Ps[64 * 36];

    uint32_t* Khi = KS;
    uint32_t* Klo = KS + 32 * 68;
    float*    KSf = (float*)KS;

    const int t    = threadIdx.x;
    const int lane = t & 31, w = t >> 5;
    const int qt   = blockIdx.x;
    const int bh   = blockIdx.y;
    const int b    = bh >> 4, h = bh & 15;
    const size_t base = (size_t)(b * SEQLEN) * D_MODEL + h * HDIM;

    // ---- stage Q (scaled by 1/tau) into KS as fp32 [64][68] ----
#pragma unroll
    for (int i = 0; i < 8; i++) {
        int id = t + i * 128;          // 0..1023
        int row = id >> 4, c4 = id & 15;
        float4 v = *(const float4*)(Q + base + (size_t)(qt * 64 + row) * D_MODEL + c4 * 4);
        KSf[row * 68 + c4 * 4 + 0] = v.x * INV_TAU;
        KSf[row * 68 + c4 * 4 + 1] = v.y * INV_TAU;
        KSf[row * 68 + c4 * 4 + 2] = v.z * INV_TAU;
        KSf[row * 68 + c4 * 4 + 3] = v.w * INV_TAU;
    }
    __syncthreads();

    // ---- load Q fragments (hi/lo) into registers ----
    uint32_t qhi[8][4], qlo[8][4];
    {
        int r = w * 16 + (lane >> 2);
#pragma unroll
        for (int k8 = 0; k8 < 8; k8++) {
            int d = (lane & 3) + k8 * 8;
            float f0 = KSf[r * 68 + d];
            float f1 = KSf[(r + 8) * 68 + d];
            float f2 = KSf[r * 68 + d + 4];
            float f3 = KSf[(r + 8) * 68 + d + 4];
            qhi[k8][0] = f2tf32(f0); qlo[k8][0] = f2tf32(f0 - __uint_as_float(qhi[k8][0]));
            qhi[k8][1] = f2tf32(f1); qlo[k8][1] = f2tf32(f1 - __uint_as_float(qhi[k8][1]));
            qhi[k8][2] = f2tf32(f2); qlo[k8][2] = f2tf32(f2 - __uint_as_float(qhi[k8][2]));
            qhi[k8][3] = f2tf32(f3); qlo[k8][3] = f2tf32(f3 - __uint_as_float(qhi[k8][3]));
        }
    }

    float o[8][4];
#pragma unroll
    for (int n8 = 0; n8 < 8; n8++)
#pragma unroll
        for (int i = 0; i < 4; i++) o[n8][i] = 0.f;
    float m0 = -1e30f, m1 = -1e30f, l0 = 0.f, l1 = 0.f;

    for (int kt = 0; kt < SEQLEN / 32; kt++) {
        __syncthreads();   // all readers of K/V/P from last tile done
        // ---- load K (hi/lo) and V (tf32) tiles ----
#pragma unroll
        for (int i = 0; i < 4; i++) {
            int id = t + i * 128;      // 0..511
            int row = id >> 4, c4 = id & 15;
            const float* kp = K + base + (size_t)(kt * 32 + row) * D_MODEL + c4 * 4;
            const float* vp = V + base + (size_t)(kt * 32 + row) * D_MODEL + c4 * 4;
            float4 kv = *(const float4*)kp;
            float4 vv = *(const float4*)vp;
            int bi = row * 68 + c4 * 4;
            const float* kf = &kv.x;
#pragma unroll
            for (int j = 0; j < 4; j++) {
                uint32_t hv = f2tf32(kf[j]);
                Khi[bi + j] = hv;
                Klo[bi + j] = f2tf32(kf[j] - __uint_as_float(hv));
            }
            const float* vf = &vv.x;
            int vi = row * 72 + c4 * 4;
#pragma unroll
            for (int j = 0; j < 4; j++) Vs[vi + j] = f2tf32(vf[j]);
        }
        __syncthreads();

        // ---- S = Q @ K^T (split: hh + hl + lh) ----
        float s[4][4];
#pragma unroll
        for (int nt = 0; nt < 4; nt++)
#pragma unroll
            for (int i = 0; i < 4; i++) s[nt][i] = 0.f;

#pragma unroll
        for (int k8 = 0; k8 < 8; k8++) {
            int d = (lane & 3) + k8 * 8;
            uint32_t bhf[4][2], blf[4][2];
#pragma unroll
            for (int nt = 0; nt < 4; nt++) {
                int n = nt * 8 + (lane >> 2);
                bhf[nt][0] = Khi[n * 68 + d];
                bhf[nt][1] = Khi[n * 68 + d + 4];
                blf[nt][0] = Klo[n * 68 + d];
                blf[nt][1] = Klo[n * 68 + d + 4];
            }
#pragma unroll
            for (int nt = 0; nt < 4; nt++) {
                mma8(s[nt], qhi[k8], bhf[nt]);
                mma8(s[nt], qhi[k8], blf[nt]);
                mma8(s[nt], qlo[k8], bhf[nt]);
            }
        }

        // ---- online softmax (rows lane>>2 and lane>>2+8) ----
        float mx0 = -1e30f, mx1 = -1e30f;
#pragma unroll
        for (int nt = 0; nt < 4; nt++) {
            mx0 = fmaxf(mx0, fmaxf(s[nt][0], s[nt][1]));
            mx1 = fmaxf(mx1, fmaxf(s[nt][2], s[nt][3]));
        }
        mx0 = fmaxf(mx0, __shfl_xor_sync(0xffffffffu, mx0, 1));
        mx0 = fmaxf(mx0, __shfl_xor_sync(0xffffffffu, mx0, 2));
        mx1 = fmaxf(mx1, __shfl_xor_sync(0xffffffffu, mx1, 1));
        mx1 = fmaxf(mx1, __shfl_xor_sync(0xffffffffu, mx1, 2));
        float mn0 = fmaxf(m0, mx0), mn1 = fmaxf(m1, mx1);
        float sc0 = __expf(m0 - mn0), sc1 = __expf(m1 - mn1);
        float sum0 = 0.f, sum1 = 0.f;
#pragma unroll
        for (int nt = 0; nt < 4; nt++) {
            s[nt][0] = __expf(s[nt][0] - mn0);
            s[nt][1] = __expf(s[nt][1] - mn0);
            s[nt][2] = __expf(s[nt][2] - mn1);
            s[nt][3] = __expf(s[nt][3] - mn1);
            sum0 += s[nt][0] + s[nt][1];
            sum1 += s[nt][2] + s[nt][3];
        }
        sum0 += __shfl_xor_sync(0xffffffffu, sum0, 1);
        sum0 += __shfl_xor_sync(0xffffffffu, sum0, 2);
        sum1 += __shfl_xor_sync(0xffffffffu, sum1, 1);
        sum1 += __shfl_xor_sync(0xffffffffu, sum1, 2);
        l0 = l0 * sc0 + sum0;  m0 = mn0;
        l1 = l1 * sc1 + sum1;  m1 = mn1;
#pragma unroll
        for (int n8 = 0; n8 < 8; n8++) {
            o[n8][0] *= sc0; o[n8][1] *= sc0;
            o[n8][2] *= sc1; o[n8][3] *= sc1;
        }

        // ---- write P to smem (per-warp rows), read back as A fragments ----
        {
            int r = w * 16 + (lane >> 2);
#pragma unroll
            for (int nt = 0; nt < 4; nt++) {
                int col = nt * 8 + (lane & 3) * 2;
                *(float2*)&Ps[r * 36 + col]       = make_float2(s[nt][0], s[nt][1]);
                *(float2*)&Ps[(r + 8) * 36 + col] = make_float2(s[nt][2], s[nt][3]);
            }
        }
        __syncwarp();

        // ---- O += P @ V ----
#pragma unroll
        for (int k8 = 0; k8 < 4; k8++) {
            uint32_t pa[4];
            {
                int r = w * 16 + (lane >> 2);
                int c = (lane & 3) + k8 * 8;
                pa[0] = f2tf32(Ps[r * 36 + c]);
                pa[1] = f2tf32(Ps[(r + 8) * 36 + c]);
                pa[2] = f2tf32(Ps[r * 36 + c + 4]);
                pa[3] = f2tf32(Ps[(r + 8) * 36 + c + 4]);
            }
#pragma unroll
            for (int n8 = 0; n8 < 8; n8++) {
                uint32_t bv[2];
                int kk = (lane & 3) + k8 * 8;
                int n  = (lane >> 2) + n8 * 8;
                bv[0] = Vs[kk * 72 + n];
                bv[1] = Vs[(kk + 4) * 72 + n];
                mma8(o[n8], pa, bv);
            }
        }
    }

    // ---- normalize + store ----
    {
        float inv0 = 1.0f / l0, inv1 = 1.0f / l1;
        int r = qt * 64 + w * 16 + (lane >> 2);
#pragma unroll
        for (int n8 = 0; n8 < 8; n8++) {
            int col = n8 * 8 + (lane & 3) * 2;
            *(float2*)(O + base + (size_t)r * D_MODEL + col) =
                make_float2(o[n8][0] * inv0, o[n8][1] * inv0);
            *(float2*)(O + base + (size_t)(r + 8) * D_MODEL + col) =
                make_float2(o[n8][2] * inv1, o[n8][3] * inv1);
        }
    }
}

// ---------------------------------------------------------------------------
extern "C" void kernel_launch(void* const* d_in, const int* in_sizes, int n_in,
                              void* d_out, int out_size)
{
    const float* q  = (const float*)d_in[0];
    const float* k  = (const float*)d_in[1];
    const float* v  = (const float*)d_in[2];
    const float* Wq = (const float*)d_in[3];
    const float* bq = (const float*)d_in[4];
    const float* Wk = (const float*)d_in[5];
    const float* bk = (const float*)d_in[6];
    const float* Wv = (const float*)d_in[7];
    const float* bv = (const float*)d_in[8];
    const float* Wo = (const float*)d_in[9];
    const float* bo = (const float*)d_in[10];
    float* out = (float*)d_out;

    float *Qp, *Kp, *Vp, *Ao;
    cudaGetSymbolAddress((void**)&Qp, g_Qp);
    cudaGetSymbolAddress((void**)&Kp, g_Kp);
    cudaGetSymbolAddress((void**)&Vp, g_Vp);
    cudaGetSymbolAddress((void**)&Ao, g_Ao);

    dim3 ggrid(D_MODEL / 128, MROWS / 128);   // (8, 64)

    gemm_tc<true><<<ggrid, 256>>>(q, Wq, bq, Qp);
    gemm_tc<true><<<ggrid, 256>>>(k, Wk, bk, Kp);
    gemm_tc<true><<<ggrid, 256>>>(v, Wv, bv, Vp);

    const int nchunks = MROWS * NHEADS;       // 131072
    l2norm_kernel<<<nchunks / 8, 256>>>(Qp, nchunks);
    l2norm_kernel<<<nchunks / 8, 256>>>(Kp, nchunks);

    attn_tc<<<dim3(SEQLEN / 64, BATCH * NHEADS), 128>>>(Qp, Kp, Vp, Ao);

    gemm_tc<true><<<ggrid, 256>>>(Ao, Wo, bo, out);
}

// round 5
// speedup vs baseline: 2.5292x; 1.6886x over previous
#include <cuda_runtime.h>
#include <cstdint>

#define D_MODEL 1024
#define SEQLEN  2048
#define BATCH   4
#define NHEADS  16
#define HDIM    64
#define MROWS   (BATCH * SEQLEN)   /* 8192 */
#define INV_TAU (1.0f / 0.07f)

// Scratch (allocation-free rule: __device__ globals)
__device__ float g_Qp[MROWS * D_MODEL];
__device__ float g_Kp[MROWS * D_MODEL];
__device__ float g_Vp[MROWS * D_MODEL];
__device__ float g_Ao[MROWS * D_MODEL];

// ---- helpers ----
__device__ __forceinline__ uint32_t f2tf32(float f) {
    uint32_t r; asm("cvt.rna.tf32.f32 %0, %1;" : "=r"(r) : "f"(f)); return r;
}
// tf32 k8 mma (used for PV only)
__device__ __forceinline__ void mma8(float* c, const uint32_t* a, const uint32_t* b) {
    asm volatile("mma.sync.aligned.m16n8k8.row.col.f32.tf32.tf32.f32 "
        "{%0,%1,%2,%3},{%4,%5,%6,%7},{%8,%9},{%0,%1,%2,%3};"
        : "+f"(c[0]), "+f"(c[1]), "+f"(c[2]), "+f"(c[3])
        : "r"(a[0]), "r"(a[1]), "r"(a[2]), "r"(a[3]), "r"(b[0]), "r"(b[1]));
}
// bf16 k16 mma
__device__ __forceinline__ void mma16(float* c, const uint32_t* a, const uint32_t* b) {
    asm volatile("mma.sync.aligned.m16n8k16.row.col.f32.bf16.bf16.f32 "
        "{%0,%1,%2,%3},{%4,%5,%6,%7},{%8,%9},{%0,%1,%2,%3};"
        : "+f"(c[0]), "+f"(c[1]), "+f"(c[2]), "+f"(c[3])
        : "r"(a[0]), "r"(a[1]), "r"(a[2]), "r"(a[3]), "r"(b[0]), "r"(b[1]));
}
// hi = truncate-to-bf16 pair (even k in low half), 1 PRMT
__device__ __forceinline__ uint32_t hipack(float e, float o) {
    return __byte_perm(__float_as_uint(e), __float_as_uint(o), 0x7632);
}
// bf16x2 round-to-nearest pack of residuals
__device__ __forceinline__ uint32_t lopack(float e, float o) {
    uint32_t r; asm("cvt.rn.bf16x2.f32 %0, %1, %2;" : "=r"(r) : "f"(o), "f"(e));
    return r;
}
__device__ __forceinline__ float truncbf(float x) {
    return __uint_as_float(__float_as_uint(x) & 0xffff0000u);
}
// split a k-pair (e,o) into hi/lo packed u32s
__device__ __forceinline__ void split2(float e, float o, uint32_t& h, uint32_t& l) {
    h = hipack(e, o);
    l = lopack(e - truncbf(e), o - truncbf(o));
}

// ---------------------------------------------------------------------------
// Split-bf16 GEMM (3-pass): C[M,N] = A[M,K] @ W[N,K]^T + bias[N]
// Block 128x128, BK=16 (= one k16 mma step), 256 threads (8 warps as 2x4),
// warp tile 64x32. Smem u32 k-pairs, stride 10 (conflict-free, STS.64-aligned).
// ---------------------------------------------------------------------------
__global__ __launch_bounds__(256) void gemm_bf3(
    const float* __restrict__ A, const float* __restrict__ W,
    const float* __restrict__ bias, float* __restrict__ C)
{
    const int K = D_MODEL, N = D_MODEL;
    __shared__ uint32_t Ah[128 * 10];
    __shared__ uint32_t Al[128 * 10];
    __shared__ uint32_t Bh[128 * 10];
    __shared__ uint32_t Bl[128 * 10];

    const int t    = threadIdx.x;
    const int lane = t & 31, wid = t >> 5;
    const int wm   = wid >> 2, wn = wid & 3;
    const int brow = blockIdx.y * 128, bcol = blockIdx.x * 128;
    const int lr   = t >> 1;            // 0..127
    const int lkp  = (t & 1) * 4;       // k-pair offset 0 or 4 (8 floats)

    const float* Ap = A + (size_t)(brow + lr) * K + lkp * 2;
    const float* Wp = W + (size_t)(bcol + lr) * K + lkp * 2;

    float acc[4][4][4];
#pragma unroll
    for (int mt = 0; mt < 4; mt++)
#pragma unroll
        for (int nt = 0; nt < 4; nt++)
#pragma unroll
            for (int i = 0; i < 4; i++) acc[mt][nt][i] = 0.f;

    float4 a0 = *(const float4*)Ap, a1 = *(const float4*)(Ap + 4);
    float4 w0 = *(const float4*)Wp, w1 = *(const float4*)(Wp + 4);

    for (int k0 = 0; k0 < K; k0 += 16) {
        __syncthreads();
        {
            const int bi = lr * 10 + lkp;
            uint32_t h, l;
            split2(a0.x, a0.y, h, l); Ah[bi + 0] = h; Al[bi + 0] = l;
            split2(a0.z, a0.w, h, l); Ah[bi + 1] = h; Al[bi + 1] = l;
            split2(a1.x, a1.y, h, l); Ah[bi + 2] = h; Al[bi + 2] = l;
            split2(a1.z, a1.w, h, l); Ah[bi + 3] = h; Al[bi + 3] = l;
            split2(w0.x, w0.y, h, l); Bh[bi + 0] = h; Bl[bi + 0] = l;
            split2(w0.z, w0.w, h, l); Bh[bi + 1] = h; Bl[bi + 1] = l;
            split2(w1.x, w1.y, h, l); Bh[bi + 2] = h; Bl[bi + 2] = l;
            split2(w1.z, w1.w, h, l); Bh[bi + 3] = h; Bl[bi + 3] = l;
        }
        __syncthreads();
        if (k0 + 16 < K) {
            Ap += 16; Wp += 16;
            a0 = *(const float4*)Ap; a1 = *(const float4*)(Ap + 4);
            w0 = *(const float4*)Wp; w1 = *(const float4*)(Wp + 4);
        }
        {
            const int kk = lane & 3;
            uint32_t ah[4][4], al[4][4], bh[4][2], bl[4][2];
#pragma unroll
            for (int mt = 0; mt < 4; mt++) {
                int r = wm * 64 + mt * 16 + (lane >> 2);
                ah[mt][0] = Ah[r * 10 + kk];
                ah[mt][1] = Ah[(r + 8) * 10 + kk];
                ah[mt][2] = Ah[r * 10 + kk + 4];
                ah[mt][3] = Ah[(r + 8) * 10 + kk + 4];
                al[mt][0] = Al[r * 10 + kk];
                al[mt][1] = Al[(r + 8) * 10 + kk];
                al[mt][2] = Al[r * 10 + kk + 4];
                al[mt][3] = Al[(r + 8) * 10 + kk + 4];
            }
#pragma unroll
            for (int nt = 0; nt < 4; nt++) {
                int n = wn * 32 + nt * 8 + (lane >> 2);
                bh[nt][0] = Bh[n * 10 + kk];
                bh[nt][1] = Bh[n * 10 + kk + 4];
                bl[nt][0] = Bl[n * 10 + kk];
                bl[nt][1] = Bl[n * 10 + kk + 4];
            }
#pragma unroll
            for (int mt = 0; mt < 4; mt++)
#pragma unroll
                for (int nt = 0; nt < 4; nt++) {
                    mma16(acc[mt][nt], ah[mt], bh[nt]);
                    mma16(acc[mt][nt], ah[mt], bl[nt]);
                    mma16(acc[mt][nt], al[mt], bh[nt]);
                }
        }
    }

#pragma unroll
    for (int mt = 0; mt < 4; mt++)
#pragma unroll
        for (int nt = 0; nt < 4; nt++) {
            int gr = brow + wm * 64 + mt * 16 + (lane >> 2);
            int gc = bcol + wn * 32 + nt * 8 + (lane & 3) * 2;
            float2 bb = *(const float2*)(bias + gc);
            float2 o0 = make_float2(acc[mt][nt][0] + bb.x, acc[mt][nt][1] + bb.y);
            float2 o1 = make_float2(acc[mt][nt][2] + bb.x, acc[mt][nt][3] + bb.y);
            *(float2*)(C + (size_t)gr * N + gc)       = o0;
            *(float2*)(C + (size_t)(gr + 8) * N + gc) = o1;
        }
}

// ---------------------------------------------------------------------------
// Per-head L2 normalize
// ---------------------------------------------------------------------------
__global__ __launch_bounds__(256) void l2norm_kernel(float* __restrict__ X, int nchunks)
{
    int gid  = blockIdx.x * blockDim.x + threadIdx.x;
    int warp = gid >> 5;
    int lane = gid & 31;
    if (warp >= nchunks) return;
    float* p = X + (size_t)warp * 64 + lane * 2;
    float2 v = *(float2*)p;
    float ss = v.x * v.x + v.y * v.y;
#pragma unroll
    for (int m = 16; m > 0; m >>= 1)
        ss += __shfl_xor_sync(0xffffffffu, ss, m);
    float inv = 1.0f / fmaxf(sqrtf(ss), 1e-12f);
    v.x *= inv; v.y *= inv;
    *(float2*)p = v;
}

// ---------------------------------------------------------------------------
// Flash attention. Grid (L/64, B*H), 128 threads (4 warps).
// QK^T: 3-pass split-bf16 (k16).  PV: single-pass tf32 (k8).
// Q hi/lo fragments in registers for the whole block.
// ---------------------------------------------------------------------------
__global__ __launch_bounds__(128) void attn_tc(
    const float* __restrict__ Q, const float* __restrict__ K,
    const float* __restrict__ V, float* __restrict__ O)
{
    __shared__ uint32_t KS[64 * 68];       // union: Q f32 staging | Khi+Klo
    __shared__ uint32_t Vs[32 * 72];       // V tf32
    __shared__ float    Ps[64 * 36];       // P f32

    uint32_t* Khi = KS;                    // [32][34] u32 k-pairs
    uint32_t* Klo = KS + 32 * 34;
    float*    KSf = (float*)KS;

    const int t    = threadIdx.x;
    const int lane = t & 31, w = t >> 5;
    const int qt   = blockIdx.x;
    const int bh   = blockIdx.y;
    const int b    = bh >> 4, h = bh & 15;
    const size_t base = (size_t)(b * SEQLEN) * D_MODEL + h * HDIM;

    // ---- stage Q (scaled by 1/tau) into KS as fp32 [64][68] ----
#pragma unroll
    for (int i = 0; i < 8; i++) {
        int id = t + i * 128;
        int row = id >> 4, c4 = id & 15;
        float4 v = *(const float4*)(Q + base + (size_t)(qt * 64 + row) * D_MODEL + c4 * 4);
        KSf[row * 68 + c4 * 4 + 0] = v.x * INV_TAU;
        KSf[row * 68 + c4 * 4 + 1] = v.y * INV_TAU;
        KSf[row * 68 + c4 * 4 + 2] = v.z * INV_TAU;
        KSf[row * 68 + c4 * 4 + 3] = v.w * INV_TAU;
    }
    __syncthreads();

    // ---- build Q hi/lo fragments (4 k16 groups) in registers ----
    uint32_t qhi[4][4], qlo[4][4];
    {
        int r = w * 16 + (lane >> 2);
#pragma unroll
        for (int g = 0; g < 4; g++) {
            int kp0 = g * 8 + (lane & 3);
#pragma unroll
            for (int u = 0; u < 4; u++) {
                int rr = (u & 1) ? r + 8 : r;
                int kp = (u & 2) ? kp0 + 4 : kp0;
                float e = KSf[rr * 68 + kp * 2];
                float o = KSf[rr * 68 + kp * 2 + 1];
                split2(e, o, qhi[g][u], qlo[g][u]);
            }
        }
    }
    __syncthreads();   // all Q frag reads done before Khi/Klo overwrite KS

    float o[8][4];
#pragma unroll
    for (int n8 = 0; n8 < 8; n8++)
#pragma unroll
        for (int i = 0; i < 4; i++) o[n8][i] = 0.f;
    float m0 = -1e30f, m1 = -1e30f, l0 = 0.f, l1 = 0.f;

    for (int kt = 0; kt < SEQLEN / 32; kt++) {
        if (kt) __syncthreads();   // previous tile's readers done
        // ---- load K (bf16 hi/lo) and V (tf32) tiles ----
#pragma unroll
        for (int i = 0; i < 4; i++) {
            int id = t + i * 128;
            int row = id >> 4, c4 = id & 15;
            float4 kv = *(const float4*)(K + base + (size_t)(kt * 32 + row) * D_MODEL + c4 * 4);
            float4 vv = *(const float4*)(V + base + (size_t)(kt * 32 + row) * D_MODEL + c4 * 4);
            int bi = row * 34 + c4 * 2;
            uint32_t hh, ll;
            split2(kv.x, kv.y, hh, ll); Khi[bi + 0] = hh; Klo[bi + 0] = ll;
            split2(kv.z, kv.w, hh, ll); Khi[bi + 1] = hh; Klo[bi + 1] = ll;
            int vi = row * 72 + c4 * 4;
            Vs[vi + 0] = f2tf32(vv.x);
            Vs[vi + 1] = f2tf32(vv.y);
            Vs[vi + 2] = f2tf32(vv.z);
            Vs[vi + 3] = f2tf32(vv.w);
        }
        __syncthreads();

        // ---- S = Q @ K^T (hh + hl + lh), 4 k16 groups ----
        float s[4][4];
#pragma unroll
        for (int nt = 0; nt < 4; nt++)
#pragma unroll
            for (int i = 0; i < 4; i++) s[nt][i] = 0.f;

#pragma unroll
        for (int g = 0; g < 4; g++) {
            int kp = g * 8 + (lane & 3);
            uint32_t bhf[4][2], blf[4][2];
#pragma unroll
            for (int nt = 0; nt < 4; nt++) {
                int n = nt * 8 + (lane >> 2);
                bhf[nt][0] = Khi[n * 34 + kp];
                bhf[nt][1] = Khi[n * 34 + kp + 4];
                blf[nt][0] = Klo[n * 34 + kp];
                blf[nt][1] = Klo[n * 34 + kp + 4];
            }
#pragma unroll
            for (int nt = 0; nt < 4; nt++) {
                mma16(s[nt], qhi[g], bhf[nt]);
                mma16(s[nt], qhi[g], blf[nt]);
                mma16(s[nt], qlo[g], bhf[nt]);
            }
        }

        // ---- online softmax (rows lane>>2 and +8) ----
        float mx0 = -1e30f, mx1 = -1e30f;
#pragma unroll
        for (int nt = 0; nt < 4; nt++) {
            mx0 = fmaxf(mx0, fmaxf(s[nt][0], s[nt][1]));
            mx1 = fmaxf(mx1, fmaxf(s[nt][2], s[nt][3]));
        }
        mx0 = fmaxf(mx0, __shfl_xor_sync(0xffffffffu, mx0, 1));
        mx0 = fmaxf(mx0, __shfl_xor_sync(0xffffffffu, mx0, 2));
        mx1 = fmaxf(mx1, __shfl_xor_sync(0xffffffffu, mx1, 1));
        mx1 = fmaxf(mx1, __shfl_xor_sync(0xffffffffu, mx1, 2));
        float mn0 = fmaxf(m0, mx0), mn1 = fmaxf(m1, mx1);
        float sc0 = __expf(m0 - mn0), sc1 = __expf(m1 - mn1);
        float sum0 = 0.f, sum1 = 0.f;
#pragma unroll
        for (int nt = 0; nt < 4; nt++) {
            s[nt][0] = __expf(s[nt][0] - mn0);
            s[nt][1] = __expf(s[nt][1] - mn0);
            s[nt][2] = __expf(s[nt][2] - mn1);
            s[nt][3] = __expf(s[nt][3] - mn1);
            sum0 += s[nt][0] + s[nt][1];
            sum1 += s[nt][2] + s[nt][3];
        }
        sum0 += __shfl_xor_sync(0xffffffffu, sum0, 1);
        sum0 += __shfl_xor_sync(0xffffffffu, sum0, 2);
        sum1 += __shfl_xor_sync(0xffffffffu, sum1, 1);
        sum1 += __shfl_xor_sync(0xffffffffu, sum1, 2);
        l0 = l0 * sc0 + sum0;  m0 = mn0;
        l1 = l1 * sc1 + sum1;  m1 = mn1;
#pragma unroll
        for (int n8 = 0; n8 < 8; n8++) {
            o[n8][0] *= sc0; o[n8][1] *= sc0;
            o[n8][2] *= sc1; o[n8][3] *= sc1;
        }

        // ---- write P (per-warp rows), consume as tf32 A fragments ----
        {
            int r = w * 16 + (lane >> 2);
#pragma unroll
            for (int nt = 0; nt < 4; nt++) {
                int col = nt * 8 + (lane & 3) * 2;
                *(float2*)&Ps[r * 36 + col]       = make_float2(s[nt][0], s[nt][1]);
                *(float2*)&Ps[(r + 8) * 36 + col] = make_float2(s[nt][2], s[nt][3]);
            }
        }
        __syncwarp();

        // ---- O += P @ V (single-pass tf32) ----
#pragma unroll
        for (int k8 = 0; k8 < 4; k8++) {
            uint32_t pa[4];
            {
                int r = w * 16 + (lane >> 2);
                int c = (lane & 3) + k8 * 8;
                pa[0] = f2tf32(Ps[r * 36 + c]);
                pa[1] = f2tf32(Ps[(r + 8) * 36 + c]);
                pa[2] = f2tf32(Ps[r * 36 + c + 4]);
                pa[3] = f2tf32(Ps[(r + 8) * 36 + c + 4]);
            }
#pragma unroll
            for (int n8 = 0; n8 < 8; n8++) {
                uint32_t bv[2];
                int kk = (lane & 3) + k8 * 8;
                int n  = (lane >> 2) + n8 * 8;
                bv[0] = Vs[kk * 72 + n];
                bv[1] = Vs[(kk + 4) * 72 + n];
                mma8(o[n8], pa, bv);
            }
        }
    }

    // ---- normalize + store ----
    {
        float inv0 = 1.0f / l0, inv1 = 1.0f / l1;
        int r = qt * 64 + w * 16 + (lane >> 2);
#pragma unroll
        for (int n8 = 0; n8 < 8; n8++) {
            int col = n8 * 8 + (lane & 3) * 2;
            *(float2*)(O + base + (size_t)r * D_MODEL + col) =
                make_float2(o[n8][0] * inv0, o[n8][1] * inv0);
            *(float2*)(O + base + (size_t)(r + 8) * D_MODEL + col) =
                make_float2(o[n8][2] * inv1, o[n8][3] * inv1);
        }
    }
}

// ---------------------------------------------------------------------------
extern "C" void kernel_launch(void* const* d_in, const int* in_sizes, int n_in,
                              void* d_out, int out_size)
{
    const float* q  = (const float*)d_in[0];
    const float* k  = (const float*)d_in[1];
    const float* v  = (const float*)d_in[2];
    const float* Wq = (const float*)d_in[3];
    const float* bq = (const float*)d_in[4];
    const float* Wk = (const float*)d_in[5];
    const float* bk = (const float*)d_in[6];
    const float* Wv = (const float*)d_in[7];
    const float* bv = (const float*)d_in[8];
    const float* Wo = (const float*)d_in[9];
    const float* bo = (const float*)d_in[10];
    float* out = (float*)d_out;

    float *Qp, *Kp, *Vp, *Ao;
    cudaGetSymbolAddress((void**)&Qp, g_Qp);
    cudaGetSymbolAddress((void**)&Kp, g_Kp);
    cudaGetSymbolAddress((void**)&Vp, g_Vp);
    cudaGetSymbolAddress((void**)&Ao, g_Ao);

    dim3 ggrid(D_MODEL / 128, MROWS / 128);   // (8, 64)

    gemm_bf3<<<ggrid, 256>>>(q, Wq, bq, Qp);
    gemm_bf3<<<ggrid, 256>>>(k, Wk, bk, Kp);
    gemm_bf3<<<ggrid, 256>>>(v, Wv, bv, Vp);

    const int nchunks = MROWS * NHEADS;       // 131072
    l2norm_kernel<<<nchunks / 8, 256>>>(Qp, nchunks);
    l2norm_kernel<<<nchunks / 8, 256>>>(Kp, nchunks);

    attn_tc<<<dim3(SEQLEN / 64, BATCH * NHEADS), 128>>>(Qp, Kp, Vp, Ao);

    gemm_bf3<<<ggrid, 256>>>(Ao, Wo, bo, out);
}